// round 13
// baseline (speedup 1.0000x reference)
#include <cuda_runtime.h>
#include <cuda_fp16.h>
#include <cstdint>

#define BATCH 32
#define T_LEN 2048
#define S_DIM 512
#define E_DIM 32
#define SLICES 4            // CTAs per batch (cluster size)
#define COLS 128            // output columns per CTA
#define NTHREADS 512
#define TARGET_EXP 6
#define ROWPAD 68           // padded words per 64-word row chunk (bank-conflict free)
#define BUFWORDS (4 * ROWPAD)          // 272 words per buffer
#define VBYTES (SLICES * 64 * 4)       // 256 half2 words per consumer per step
#define ZFBYTES (SLICES * 16 * 4)      // final z: 64 fp32 partials

__device__ int g_obs[BATCH * T_LEN];

__global__ void obs_extract_kernel(const float* __restrict__ inputs) {
    int idx = blockIdx.x * blockDim.x + threadIdx.x;
    if (idx >= BATCH * T_LEN) return;
    const float* p = inputs + (size_t)idx * E_DIM;
    int e = 0;
#pragma unroll
    for (int i = 0; i < E_DIM; i++) {
        if (p[i] > 0.5f) e = i;
    }
    g_obs[idx] = e;
}

__device__ __forceinline__ uint32_t smem_u32(const void* p) {
    uint32_t a;
    asm("{ .reg .u64 t; cvta.to.shared.u64 t, %1; cvt.u32.u64 %0, t; }"
        : "=r"(a) : "l"(p));
    return a;
}

__device__ __forceinline__ uint32_t mapa_u32(uint32_t saddr, uint32_t rank) {
    uint32_t ra;
    asm("mapa.shared::cluster.u32 %0, %1, %2;" : "=r"(ra) : "r"(saddr), "r"(rank));
    return ra;
}

__device__ __forceinline__ void cluster_sync_() {
    asm volatile("barrier.cluster.arrive.aligned;" ::: "memory");
    asm volatile("barrier.cluster.wait.aligned;" ::: "memory");
}

__device__ __forceinline__ void st_async_u32(uint32_t raddr, uint32_t v, uint32_t rmbar) {
    asm volatile(
        "st.async.shared::cluster.mbarrier::complete_tx::bytes.b32 [%0], %1, [%2];"
        :: "r"(raddr), "r"(v), "r"(rmbar) : "memory");
}

// remote cluster-smem atomic add (u32 fixed point) — consumed >=1 full step later
__device__ __forceinline__ void red_add_cluster_u32(uint32_t raddr, uint32_t v) {
    asm volatile("red.relaxed.cluster.shared::cluster.add.u32 [%0], %1;"
                 :: "r"(raddr), "r"(v) : "memory");
}

__device__ __forceinline__ void mbar_init(uint32_t mbar, uint32_t cnt) {
    asm volatile("mbarrier.init.shared.b64 [%0], %1;" :: "r"(mbar), "r"(cnt) : "memory");
}

__device__ __forceinline__ void mbar_expect_tx(uint32_t mbar, uint32_t bytes) {
    asm volatile("mbarrier.arrive.expect_tx.shared.b64 _, [%0], %1;"
                 :: "r"(mbar), "r"(bytes) : "memory");
}

__device__ __forceinline__ void mbar_wait_parity(uint32_t mbar, uint32_t parity) {
    asm volatile(
        "{\n\t"
        ".reg .pred P;\n\t"
        "WAIT_%=: \n\t"
        "mbarrier.try_wait.parity.acquire.cluster.shared::cta.b64 P, [%0], %1, 0x989680;\n\t"
        "@!P bra WAIT_%=;\n\t"
        "}"
        :: "r"(mbar), "r"(parity) : "memory");
}

__global__ void __cluster_dims__(SLICES, 1, 1) __launch_bounds__(NTHREADS, 1)
hmm_forward_kernel(const float* __restrict__ A,
                   const float* __restrict__ Bem,
                   const float* __restrict__ pi,
                   float* __restrict__ out)
{
    __shared__ __align__(16) uint32_t alpha2[2][BUFWORDS]; // padded half2 buffers
    __shared__ __align__(16) uint32_t zrem[4];             // fixed-point Z ring
    __shared__ __align__(16) float    zfin[SLICES * 16];   // final-step exact z
    __shared__ float    bem_t[E_DIM][COLS];
    __shared__ float    embias[E_DIM];
    __shared__ int      obs_s[T_LEN];
    __shared__ __align__(8) unsigned long long mbar_store[3]; // v0, v1, zfin

    const int tid = threadIdx.x;
    const int w = tid >> 5;
    const int l = tid & 31;
    const int r  = l >> 3;          // row chunk 0..3 (128 rows each)
    const int cl = l & 7;           // column within warp's 8
    uint32_t crank;
    asm("mov.u32 %0, %%cluster_ctarank;" : "=r"(crank));
    const int c = (int)crank;
    const int b = blockIdx.x / SLICES;

    const int colc = 8 * w + cl;          // column within CTA slice
    const int jg = c * COLS + colc;       // global column

    // ---- A slice into registers: a2[p] = {A[128r+2p][jg], A[128r+2p+1][jg]} ----
    __half2 a2[64];
#pragma unroll
    for (int p = 0; p < 64; p++) {
        float r0 = A[(size_t)(128 * r + 2 * p) * S_DIM + jg];
        float r1 = A[(size_t)(128 * r + 2 * p + 1) * S_DIM + jg];
        a2[p] = __floats2half2_rn(r0, r1);
    }

    for (int i = tid; i < E_DIM * COLS; i += NTHREADS) {
        int e = i / COLS, j = i % COLS;
        bem_t[e][j] = Bem[(size_t)(c * COLS + j) * E_DIM + e];
    }
    for (int i = tid; i < T_LEN; i += NTHREADS) obs_s[i] = g_obs[b * T_LEN + i];
    if (tid < 4) zrem[tid] = 0u;

    // ---- per-symbol mean emission (lagged scale estimate) ----
    {
        int e = tid >> 4, seg = tid & 15;
        float s = 0.0f;
#pragma unroll 4
        for (int i = 0; i < 32; i++)
            s += Bem[(size_t)(seg * 32 + i) * E_DIM + e];
#pragma unroll
        for (int o = 8; o > 0; o >>= 1)
            s += __shfl_xor_sync(0xffffffffu, s, o);
        if (seg == 0) embias[e] = s * (1.0f / 512.0f);
    }

    const uint32_t val_sa  = smem_u32(&alpha2[0][0]);
    const uint32_t z_sa    = smem_u32(&zrem[0]);
    const uint32_t zf_sa   = smem_u32(&zfin[0]);
    const uint32_t mbar_sa = smem_u32(&mbar_store[0]);
    // mbar: v[buf] = buf*8 ; zfin = 16

    if (tid == 0) {
#pragma unroll
        for (int i = 0; i < 3; i++) mbar_init(mbar_sa + i * 8, 1);
        mbar_expect_tx(mbar_sa + 16, ZFBYTES);   // final-z expect, posted once
    }
    __syncthreads();
    cluster_sync_();   // peers' mbarriers + smem ready before any remote store

    // per-lane hoisted remote addresses (scalars, no arrays)
    const uint32_t my_val_r = mapa_u32(val_sa, (uint32_t)r);   // value target rank = r
    const uint32_t my_mb_r  = mapa_u32(mbar_sa, (uint32_t)r);
    const uint32_t my_z_r   = mapa_u32(z_sa, (uint32_t)(l & 3));  // z target rank = l (lanes 0-3)
    const uint32_t my_zf_r  = mapa_u32(zf_sa, (uint32_t)(l & 3));
    const uint32_t my_mbzf  = mapa_u32(mbar_sa, (uint32_t)(l & 3)) + 16;
    const uint32_t ship_off = (uint32_t)(4 * (ROWPAD * c + 4 * w + (cl >> 1)));
    const bool ship_v = !(l & 1);

    // ---- PROLOGUE: w_0 = 2^TARGET * pi .* em_0 -> buf 0 ; z(0) -> ring slot 0 ----
    {
        const int e0 = obs_s[0];
        float m = pi[jg] * bem_t[e0][colc] * (float)(1 << TARGET_EXP);
        float mh = __shfl_down_sync(0xffffffffu, m, 1);
        if (ship_v) {
            __half2 h = __floats2half2_rn(m, mh);
            st_async_u32(my_val_r + ship_off, *reinterpret_cast<uint32_t*>(&h),
                         my_mb_r + 0);
        }
        float z = m;
        z += __shfl_xor_sync(0xffffffffu, z, 1);
        z += __shfl_xor_sync(0xffffffffu, z, 2);
        z += __shfl_xor_sync(0xffffffffu, z, 4);   // 8-col warp partial
        if (l < 4) red_add_cluster_u32(my_z_r + 0 * 4, (uint32_t)(z * 256.0f));
    }

    int K = TARGET_EXP;
    int d_prev = 0;

    for (int t = 0; t < T_LEN - 1; t++) {
        const int buf = t & 1;
        const int nbuf = buf ^ 1;
        const uint32_t par = (uint32_t)((t >> 1) & 1);

        if (tid == 0) mbar_expect_tx(mbar_sa + buf * 8, VBYTES);
        if (w == 1 && l == 0) *(volatile uint32_t*)&zrem[(t + 2) & 3] = 0u; // zero ahead

        // ---- scale compute (all warps, redundant, pre-wait; lagged Z) ----
        const int en = obs_s[t + 1];
        float Zm;
        int dp;
        if (t == 0) {
            Zm = (float)(1 << TARGET_EXP) * embias[obs_s[0]] * embias[en];
            dp = 0;
        } else {
            uint32_t zu = *(volatile uint32_t*)&zrem[(t - 1) & 3];
            Zm = (float)zu * (1.0f / 256.0f) * embias[obs_s[t]] * embias[en];
            dp = d_prev;
        }
        int ex = ((__float_as_int(Zm) >> 23) & 255) - 127;
        int d = TARGET_EXP - ex - dp;
        d = d < -48 ? -48 : (d > 48 ? 48 : d);
        float scale = __int_as_float((uint32_t)(d + 127) << 23);
        d_prev = d;
        K += d;

        // ---- wait for values, matvec (no CTA barrier anywhere) ----
        mbar_wait_parity(mbar_sa + buf * 8, par);

        __half2 acc0 = __float2half2_rn(0.0f);
        __half2 acc1 = acc0;
        const uint4* ab = reinterpret_cast<const uint4*>(&alpha2[buf][ROWPAD * r]);
#pragma unroll
        for (int q = 0; q < 16; q++) {
            uint4 av = ab[q];
            acc0 = __hfma2(*reinterpret_cast<__half2*>(&av.x), a2[4 * q + 0], acc0);
            acc1 = __hfma2(*reinterpret_cast<__half2*>(&av.y), a2[4 * q + 1], acc1);
            acc0 = __hfma2(*reinterpret_cast<__half2*>(&av.z), a2[4 * q + 2], acc0);
            acc1 = __hfma2(*reinterpret_cast<__half2*>(&av.w), a2[4 * q + 3], acc1);
        }
        acc0 = __hadd2(acc0, acc1);
        float2 f0 = __half22float2(acc0);
        float s = f0.x + f0.y;
        s += __shfl_xor_sync(0xffffffffu, s, 8);    // combine 4 row chunks
        s += __shfl_xor_sync(0xffffffffu, s, 16);   // -> full column sum in every lane

        float m = s * bem_t[en][colc] * scale;
        float mh = __shfl_down_sync(0xffffffffu, m, 1);
        if (ship_v) {
            __half2 h = __floats2half2_rn(m, mh);
            st_async_u32(my_val_r + (uint32_t)(nbuf * BUFWORDS * 4) + ship_off,
                         *reinterpret_cast<uint32_t*>(&h), my_mb_r + nbuf * 8);
        }

        // z partial (8 cols): fixed-point red into every CTA's ring slot
        float z = m;
        z += __shfl_xor_sync(0xffffffffu, z, 1);
        z += __shfl_xor_sync(0xffffffffu, z, 2);
        z += __shfl_xor_sync(0xffffffffu, z, 4);
        if (l < 4) {
            red_add_cluster_u32(my_z_r + (uint32_t)(((t + 1) & 3) * 4),
                                (uint32_t)(z * 256.0f));
            if (t == T_LEN - 2)   // exact final z via tx-counted mbarrier
                st_async_u32(my_zf_r + (uint32_t)((c * 16 + w) * 4),
                             __float_as_uint(z), my_mbzf);
        }
    }

    // ---- FINAL: exact Z(T-1) ----
    mbar_wait_parity(mbar_sa + 16, 0);
    if (c == 0 && tid == 0) {
        float Z = 0.0f;
#pragma unroll
        for (int i = 0; i < SLICES * 16; i++) Z += zfin[i];
        out[b] = (log2f(Z) - (float)K) * 0.6931471805599453f;
    }
    cluster_sync_();   // no CTA exits while peers may still target its smem
}

extern "C" void kernel_launch(void* const* d_in, const int* in_sizes, int n_in,
                              void* d_out, int out_size)
{
    const float* inputs = (const float*)d_in[0];  // [B,T,E] one-hot
    const float* A      = (const float*)d_in[1];  // [S,S]
    const float* Bem    = (const float*)d_in[2];  // [S,E]
    const float* pi     = (const float*)d_in[3];  // [S]
    float* out = (float*)d_out;                   // [B]

    obs_extract_kernel<<<(BATCH * T_LEN + 255) / 256, 256>>>(inputs);
    hmm_forward_kernel<<<BATCH * SLICES, NTHREADS>>>(A, Bem, pi, out);
}